// round 12
// baseline (speedup 1.0000x reference)
#include <cuda_runtime.h>
#include <cuda_fp16.h>
#include <math.h>
#include <float.h>
#include <stdint.h>

#define N_PRED 8192
#define M_TGT  16384
#define KD     128
#define MT     128                // CTA tile M
#define NT     256                // CTA tile N
#define NITEMS 4096               // 64 pred-tiles * 64 chunks
#define NCTA   148                // 1 per SM
#define TOPK   5
#define ROWB   272                // padded smem row bytes (136 halves)

// ---------------- static device scratch ----------------
__device__ __half g_pred_h[N_PRED * KD];
__device__ __half g_tgt_h[M_TGT * KD];
__device__ float  g_a2[N_PRED];
__device__ __half g_b2h[M_TGT];
// writer-indexed candidates: [cta][ptslot(2)][warpN(4)][128 rows][5]
__device__ float  g_cand2[NCTA * 2 * 4 * 128 * TOPK];
__device__ float  g_partials[32];
__device__ int    g_ticket;

// ---------------- smem layout (bytes), total 175104 ----------------
#define SA    0
#define SB0   34816
#define SB1   104448
#define B2H0  174080
#define B2H1  174592
#define SMEM_TOTAL 175104

__device__ __forceinline__ uint32_t smem_u32(const void* p) {
    uint32_t a;
    asm("{ .reg .u64 t; cvta.to.shared.u64 t, %1; cvt.u32.u64 %0, t; }"
        : "=r"(a) : "l"(p));
    return a;
}
__device__ __forceinline__ void cp16(uint32_t dst, const void* src) {
    asm volatile("cp.async.cg.shared.global [%0], [%1], 16;"
                 :: "r"(dst), "l"(src) : "memory");
}
__device__ __forceinline__ void cp4(uint32_t dst, const void* src) {
    asm volatile("cp.async.ca.shared.global [%0], [%1], 4;"
                 :: "r"(dst), "l"(src) : "memory");
}
#define CP_COMMIT() asm volatile("cp.async.commit_group;" ::: "memory")
#define CP_WAIT0()  asm volatile("cp.async.wait_group 0;" ::: "memory")

__device__ __forceinline__ void ldsm4(uint32_t a, uint32_t& r0, uint32_t& r1,
                                      uint32_t& r2, uint32_t& r3) {
    asm volatile("ldmatrix.sync.aligned.m8n8.x4.shared.b16 {%0,%1,%2,%3}, [%4];"
                 : "=r"(r0), "=r"(r1), "=r"(r2), "=r"(r3) : "r"(a));
}
__device__ __forceinline__ void mma16816_f16(uint32_t& d0, uint32_t& d1,
                                             uint32_t a0, uint32_t a1,
                                             uint32_t a2, uint32_t a3,
                                             uint32_t b0, uint32_t b1) {
    asm volatile("mma.sync.aligned.m16n8k16.row.col.f16.f16.f16.f16 "
                 "{%0,%1}, {%2,%3,%4,%5}, {%6,%7}, {%0,%1};"
                 : "+r"(d0), "+r"(d1)
                 : "r"(a0), "r"(a1), "r"(a2), "r"(a3), "r"(b0), "r"(b1));
}

#define CE(x, y) { float _lo = fminf(x, y); float _hi = fmaxf(x, y); x = _lo; y = _hi; }
#define INS(t, v) \
    if ((v) < (t)[4]) { \
        (t)[4] = (v); \
        CE((t)[3], (t)[4]); CE((t)[2], (t)[3]); \
        CE((t)[1], (t)[2]); CE((t)[0], (t)[1]); \
    }

// static partition: 4096 = 148*27 + 100
__host__ __device__ __forceinline__ int part_start(int cta) {
    return cta * 27 + (cta < 100 ? cta : 100);
}
__device__ __forceinline__ int cta_of(int item) {
    return (item < 2800) ? (item / 28) : ((item - 100) / 27);
}

// ---------------- prep: fp32 -> fp16 + norms ----------------
__global__ void prep_kernel(const float* __restrict__ pred,
                            const float* __restrict__ tgt) {
    if (blockIdx.x == 0 && threadIdx.x == 0) g_ticket = 0;
    int row  = blockIdx.x * 8 + (threadIdx.x >> 5);
    int lane = threadIdx.x & 31;
    if (row >= N_PRED + M_TGT) return;
    const float* src = (row < M_TGT) ? (tgt + (size_t)row * KD)
                                     : (pred + (size_t)(row - M_TGT) * KD);
    float4 v = ((const float4*)src)[lane];
    float s = v.x * v.x + v.y * v.y + v.z * v.z + v.w * v.w;
    #pragma unroll
    for (int off = 16; off; off >>= 1)
        s += __shfl_xor_sync(0xffffffffu, s, off);
    __half2 h0 = __floats2half2_rn(v.x, v.y);
    __half2 h1 = __floats2half2_rn(v.z, v.w);
    uint2 u;
    u.x = *reinterpret_cast<unsigned*>(&h0);
    u.y = *reinterpret_cast<unsigned*>(&h1);
    __half* dst = (row < M_TGT) ? (g_tgt_h + (size_t)row * KD)
                                : (g_pred_h + (size_t)(row - M_TGT) * KD);
    *(uint2*)(dst + lane * 4) = u;
    if (lane == 0) {
        if (row < M_TGT) g_b2h[row] = __float2half_rn(s);
        else             g_a2[row - M_TGT] = s;
    }
}

// ---------------- main: 64x64 warp-tile HMMA + half2 stream-min ----------------
extern __shared__ char smem[];

__device__ __forceinline__ void flush_sm5(__half2 (&sm5)[8][8], int cta, int slot,
                                          int warpM, int warpN, int lane) {
    float t5[8][TOPK];
    #pragma unroll
    for (int r = 0; r < 8; r++)
        #pragma unroll
        for (int s = 0; s < TOPK; s++) t5[r][s] = FLT_MAX;
    #pragma unroll
    for (int r = 0; r < 8; r++)
        #pragma unroll
        for (int nf = 0; nf < 8; nf++) {
            float2 f = __half22float2(sm5[r][nf]);
            INS(t5[r], f.x);
            INS(t5[r], f.y);
        }
    // quad merge: lanes 4g..4g+3 share the same rows
    #pragma unroll
    for (int r = 0; r < 8; r++) {
        #pragma unroll
        for (int off = 1; off <= 2; off <<= 1) {
            float b[TOPK], m[TOPK];
            #pragma unroll
            for (int s = 0; s < TOPK; s++)
                b[s] = __shfl_xor_sync(0xffffffffu, t5[r][s], off);
            #pragma unroll
            for (int s = 0; s < TOPK; s++)
                m[s] = fminf(t5[r][s], b[TOPK - 1 - s]);
            CE(m[0], m[1]); CE(m[1], m[2]); CE(m[2], m[3]); CE(m[3], m[4]);
            CE(m[0], m[1]); CE(m[1], m[2]); CE(m[2], m[3]);
            CE(m[0], m[1]); CE(m[1], m[2]);
            CE(m[0], m[1]);
            #pragma unroll
            for (int s = 0; s < TOPK; s++) t5[r][s] = m[s];
        }
    }
    if ((lane & 3) == 0) {
        #pragma unroll
        for (int mf = 0; mf < 4; mf++)
            #pragma unroll
            for (int h = 0; h < 2; h++) {
                int lrow = warpM * 64 + mf * 16 + (lane >> 2) + 8 * h;
                size_t base =
                    ((((size_t)cta * 2 + slot) * 4 + warpN) * 128 + lrow) * TOPK;
                #pragma unroll
                for (int s = 0; s < TOPK; s++)
                    g_cand2[base + s] = t5[mf * 2 + h][s];
            }
    }
}

__global__ __launch_bounds__(256, 1) void mma_main() {
    const int tid   = threadIdx.x;
    const int wid   = tid >> 5;
    const int lane  = tid & 31;
    const int warpM = wid >> 2;      // 0..1 (64 rows each)
    const int warpN = wid & 3;       // 0..3 (64 cols each)
    const int cta   = blockIdx.x;
    const uint32_t sbase = smem_u32(smem);

    const int start = part_start(cta);
    const int end   = part_start(cta + 1);

    const uint32_t rowA_off =
        (uint32_t)(warpM * 64 + ((lane >> 3) & 1) * 8 + (lane & 7)) * ROWB +
        (uint32_t)(lane >> 4) * 16;
    const uint32_t rowB_off =
        (uint32_t)(warpN * 64 + ((lane >> 4) & 1) * 8 + (lane & 7)) * ROWB +
        (uint32_t)((lane >> 3) & 1) * 16;

    const __half2 HINF2 = __half2half2(__ushort_as_half((unsigned short)0x7C00));
    const __half2 NEG2  = __float2half2_rn(-2.0f);

    __half2 sm5[8][8];
    #pragma unroll
    for (int r = 0; r < 8; r++)
        #pragma unroll
        for (int nf = 0; nf < 8; nf++) sm5[r][nf] = HINF2;

    // prime B for first item (256 rows = 4096 cp16 chunks)
    {
        const int tb = (start & 63) * NT;
        const char* gB = (const char*)g_tgt_h + (size_t)tb * 256;
        #pragma unroll
        for (int i = 0; i < 16; i++) {
            int cix = tid + i * 256;
            int r = cix >> 4, c = cix & 15;
            cp16(sbase + SB0 + r * ROWB + c * 16, gB + (size_t)r * 256 + c * 16);
        }
        if (tid < 128) cp4(sbase + B2H0 + tid * 4, g_b2h + tb + tid * 2);
        CP_COMMIT();
    }

    int cur_pt = -1, slotidx = -1;

    for (int it = start; it < end; it++) {
        const int pt = it >> 6;
        const int p  = (it - start) & 1;
        const uint32_t sb_cur = sbase + (p ? SB1 : SB0);
        const uint32_t b2_cur = sbase + (p ? B2H1 : B2H0);

        if (pt != cur_pt) {
            if (cur_pt >= 0) {
                flush_sm5(sm5, cta, slotidx, warpM, warpN, lane);
                #pragma unroll
                for (int r = 0; r < 8; r++)
                    #pragma unroll
                    for (int nf = 0; nf < 8; nf++) sm5[r][nf] = HINF2;
            }
            cur_pt = pt;
            slotidx++;
            const char* gA = (const char*)g_pred_h + (size_t)pt * MT * 256;
            #pragma unroll
            for (int i = 0; i < 8; i++) {
                int cix = tid + i * 256;
                int r = cix >> 4, c = cix & 15;
                cp16(sbase + SA + r * ROWB + c * 16, gA + (size_t)r * 256 + c * 16);
            }
            CP_COMMIT();
            CP_WAIT0();
            __syncthreads();
        }

        // prefetch next B tile
        if (it + 1 < end) {
            const int tbn = ((it + 1) & 63) * NT;
            const uint32_t sb_nxt = sbase + (p ? SB0 : SB1);
            const uint32_t b2_nxt = sbase + (p ? B2H0 : B2H1);
            const char* gB = (const char*)g_tgt_h + (size_t)tbn * 256;
            #pragma unroll
            for (int i = 0; i < 16; i++) {
                int cix = tid + i * 256;
                int r = cix >> 4, c = cix & 15;
                cp16(sb_nxt + r * ROWB + c * 16, gB + (size_t)r * 256 + c * 16);
            }
            if (tid < 128) cp4(b2_nxt + tid * 4, g_b2h + tbn + tid * 2);
            CP_COMMIT();
        }

        // ---- C(64x64, f16 acc) = A_warp(64x128) . B_warp^T ----
        uint32_t acc[4][8][2];
        #pragma unroll
        for (int mf = 0; mf < 4; mf++)
            #pragma unroll
            for (int nf = 0; nf < 8; nf++) {
                acc[mf][nf][0] = 0u;
                acc[mf][nf][1] = 0u;
            }

        #pragma unroll
        for (int ks = 0; ks < 8; ks++) {
            uint32_t a[4][4];
            #pragma unroll
            for (int mf = 0; mf < 4; mf++)
                ldsm4(sbase + SA + rowA_off + mf * (16 * ROWB) + ks * 32,
                      a[mf][0], a[mf][1], a[mf][2], a[mf][3]);
            #pragma unroll
            for (int j = 0; j < 4; j++) {
                uint32_t b0, b1, b2, b3;
                ldsm4(sb_cur + rowB_off + j * (16 * ROWB) + ks * 32, b0, b1, b2, b3);
                #pragma unroll
                for (int mf = 0; mf < 4; mf++) {
                    mma16816_f16(acc[mf][2 * j + 0][0], acc[mf][2 * j + 0][1],
                                 a[mf][0], a[mf][1], a[mf][2], a[mf][3], b0, b1);
                    mma16816_f16(acc[mf][2 * j + 1][0], acc[mf][2 * j + 1][1],
                                 a[mf][0], a[mf][1], a[mf][2], a[mf][3], b2, b3);
                }
            }
        }

        // ---- epilogue: half2 keys + unconditional stream-min ----
        #pragma unroll
        for (int nf = 0; nf < 8; nf++) {
            uint32_t b2r;
            asm volatile("ld.shared.b32 %0, [%1];" : "=r"(b2r)
                : "r"(b2_cur + (uint32_t)(warpN * 128 + nf * 16 + 4 * (lane & 3))));
            __half2 b2h2 = *reinterpret_cast<__half2*>(&b2r);
            #pragma unroll
            for (int mf = 0; mf < 4; mf++)
                #pragma unroll
                for (int h = 0; h < 2; h++) {
                    __half2 a = *reinterpret_cast<__half2*>(&acc[mf][nf][h]);
                    __half2 key = __hfma2(NEG2, a, b2h2);
                    sm5[mf * 2 + h][nf] = __hmin2(sm5[mf * 2 + h][nf], key);
                }
        }

        CP_WAIT0();
        __syncthreads();
    }

    flush_sm5(sm5, cta, slotidx, warpM, warpN, lane);
}

// ---------------- merge writer-indexed candidates -> final ----------------
__global__ void merge_kernel(float* __restrict__ out) {
    __shared__ float ws[8];
    __shared__ int is_last;
    int r  = blockIdx.x * 256 + threadIdx.x;
    int pt = r >> 7;
    int lr = r & 127;
    int w0 = cta_of(pt << 6);
    int w1 = cta_of((pt << 6) + 63);

    float t5[TOPK];
    #pragma unroll
    for (int s = 0; s < TOPK; s++) t5[s] = FLT_MAX;

    for (int w = w0; w <= w1; w++) {
        int slot = ((part_start(w) >> 6) == pt) ? 0 : 1;
        #pragma unroll
        for (int wn = 0; wn < 4; wn++) {
            size_t base = ((((size_t)w * 2 + slot) * 4 + wn) * 128 + lr) * TOPK;
            #pragma unroll
            for (int s = 0; s < TOPK; s++) {
                float key = g_cand2[base + s];
                INS(t5, key);
            }
        }
    }

    float a2 = g_a2[r];
    float sum = 0.0f;
    #pragma unroll
    for (int s = 0; s < TOPK; s++) {
        float d2 = fmaxf(a2 + t5[s], 0.0f);
        sum += fmaxf(sqrtf(d2) - 1.0f, 0.0f);
    }
    #pragma unroll
    for (int off = 16; off; off >>= 1)
        sum += __shfl_xor_sync(0xffffffffu, sum, off);
    if ((threadIdx.x & 31) == 0) ws[threadIdx.x >> 5] = sum;
    __syncthreads();
    if (threadIdx.x == 0) {
        float t = 0.0f;
        #pragma unroll
        for (int w = 0; w < 8; w++) t += ws[w];
        g_partials[blockIdx.x] = t;
        __threadfence();
        int v = atomicAdd(&g_ticket, 1);
        is_last = (v == 31) ? 1 : 0;
    }
    __syncthreads();
    if (is_last && threadIdx.x == 0) {
        __threadfence();
        float t = 0.0f;
        #pragma unroll
        for (int b = 0; b < 32; b++) t += g_partials[b];   // fixed order
        out[0] = t * (1.0f / ((float)N_PRED * (float)TOPK));
    }
}

extern "C" void kernel_launch(void* const* d_in, const int* in_sizes, int n_in,
                              void* d_out, int out_size) {
    const float* pred = (const float*)d_in[0];
    const float* tgt  = (const float*)d_in[1];

    prep_kernel<<<(N_PRED + M_TGT + 7) / 8, 256>>>(pred, tgt);

    cudaFuncSetAttribute(mma_main, cudaFuncAttributeMaxDynamicSharedMemorySize,
                         SMEM_TOTAL);
    mma_main<<<NCTA, 256, SMEM_TOTAL>>>();

    merge_kernel<<<N_PRED / 256, 256>>>((float*)d_out);
}

// round 13
// speedup vs baseline: 1.0167x; 1.0167x over previous
#include <cuda_runtime.h>
#include <cuda_fp16.h>
#include <math.h>
#include <float.h>
#include <stdint.h>

#define N_PRED 8192
#define M_TGT  16384
#define KD     128
#define MT     128                // CTA tile M
#define NT     256                // CTA tile N
#define NITEMS 4096               // 64 pred-tiles * 64 chunks
#define NCTA   148                // 1 per SM
#define TOPK   5
#define ROWB   272                // padded smem row bytes (136 halves)

// ---------------- static device scratch ----------------
__device__ __half g_pred_h[N_PRED * KD];
__device__ __half g_tgt_h[M_TGT * KD];
__device__ float  g_a2[N_PRED];
__device__ __half g_b2h[M_TGT];
// writer-indexed candidates: [cta][ptslot(2)][warpN(4)][128 rows][5]
__device__ float  g_cand2[NCTA * 2 * 4 * 128 * TOPK];
__device__ float  g_partials[32];
__device__ int    g_ticket;

// ---------------- smem layout (bytes), total 175104 ----------------
#define SA    0
#define SB0   34816
#define SB1   104448
#define B2H0  174080
#define B2H1  174592
#define SMEM_TOTAL 175104

__device__ __forceinline__ uint32_t smem_u32(const void* p) {
    uint32_t a;
    asm("{ .reg .u64 t; cvta.to.shared.u64 t, %1; cvt.u32.u64 %0, t; }"
        : "=r"(a) : "l"(p));
    return a;
}
__device__ __forceinline__ void cp16(uint32_t dst, const void* src) {
    asm volatile("cp.async.cg.shared.global [%0], [%1], 16;"
                 :: "r"(dst), "l"(src) : "memory");
}
__device__ __forceinline__ void cp4(uint32_t dst, const void* src) {
    asm volatile("cp.async.ca.shared.global [%0], [%1], 4;"
                 :: "r"(dst), "l"(src) : "memory");
}
#define CP_COMMIT() asm volatile("cp.async.commit_group;" ::: "memory")
#define CP_WAIT0()  asm volatile("cp.async.wait_group 0;" ::: "memory")

__device__ __forceinline__ void ldsm4(uint32_t a, uint32_t& r0, uint32_t& r1,
                                      uint32_t& r2, uint32_t& r3) {
    asm volatile("ldmatrix.sync.aligned.m8n8.x4.shared.b16 {%0,%1,%2,%3}, [%4];"
                 : "=r"(r0), "=r"(r1), "=r"(r2), "=r"(r3) : "r"(a));
}
__device__ __forceinline__ void mma16816_f16(uint32_t& d0, uint32_t& d1,
                                             uint32_t a0, uint32_t a1,
                                             uint32_t a2, uint32_t a3,
                                             uint32_t b0, uint32_t b1) {
    asm volatile("mma.sync.aligned.m16n8k16.row.col.f16.f16.f16.f16 "
                 "{%0,%1}, {%2,%3,%4,%5}, {%6,%7}, {%0,%1};"
                 : "+r"(d0), "+r"(d1)
                 : "r"(a0), "r"(a1), "r"(a2), "r"(a3), "r"(b0), "r"(b1));
}

#define CE(x, y) { float _lo = fminf(x, y); float _hi = fmaxf(x, y); x = _lo; y = _hi; }
#define INS(t, v) \
    if ((v) < (t)[4]) { \
        (t)[4] = (v); \
        CE((t)[3], (t)[4]); CE((t)[2], (t)[3]); \
        CE((t)[1], (t)[2]); CE((t)[0], (t)[1]); \
    }

// static partition: 4096 = 148*27 + 100
__host__ __device__ __forceinline__ int part_start(int cta) {
    return cta * 27 + (cta < 100 ? cta : 100);
}
__device__ __forceinline__ int cta_of(int item) {
    return (item < 2800) ? (item / 28) : ((item - 100) / 27);
}

// ---------------- prep: fp32 -> fp16 + norms ----------------
__global__ void prep_kernel(const float* __restrict__ pred,
                            const float* __restrict__ tgt) {
    if (blockIdx.x == 0 && threadIdx.x == 0) g_ticket = 0;
    int row  = blockIdx.x * 8 + (threadIdx.x >> 5);
    int lane = threadIdx.x & 31;
    if (row >= N_PRED + M_TGT) return;
    const float* src = (row < M_TGT) ? (tgt + (size_t)row * KD)
                                     : (pred + (size_t)(row - M_TGT) * KD);
    float4 v = ((const float4*)src)[lane];
    float s = v.x * v.x + v.y * v.y + v.z * v.z + v.w * v.w;
    #pragma unroll
    for (int off = 16; off; off >>= 1)
        s += __shfl_xor_sync(0xffffffffu, s, off);
    __half2 h0 = __floats2half2_rn(v.x, v.y);
    __half2 h1 = __floats2half2_rn(v.z, v.w);
    uint2 u;
    u.x = *reinterpret_cast<unsigned*>(&h0);
    u.y = *reinterpret_cast<unsigned*>(&h1);
    __half* dst = (row < M_TGT) ? (g_tgt_h + (size_t)row * KD)
                                : (g_pred_h + (size_t)(row - M_TGT) * KD);
    *(uint2*)(dst + lane * 4) = u;
    if (lane == 0) {
        if (row < M_TGT) g_b2h[row] = __float2half_rn(s);
        else             g_a2[row - M_TGT] = s;
    }
}

// ---------------- main: 64x64 warp-tile HMMA + cached A-frags ----------------
extern __shared__ char smem[];

__device__ __forceinline__ void flush_sm5(__half2 (&sm5)[8][8], int cta, int slot,
                                          int warpM, int warpN, int lane) {
    float t5[8][TOPK];
    #pragma unroll
    for (int r = 0; r < 8; r++)
        #pragma unroll
        for (int s = 0; s < TOPK; s++) t5[r][s] = FLT_MAX;
    #pragma unroll
    for (int r = 0; r < 8; r++)
        #pragma unroll
        for (int nf = 0; nf < 8; nf++) {
            float2 f = __half22float2(sm5[r][nf]);
            INS(t5[r], f.x);
            INS(t5[r], f.y);
        }
    // quad merge: lanes 4g..4g+3 share the same rows
    #pragma unroll
    for (int r = 0; r < 8; r++) {
        #pragma unroll
        for (int off = 1; off <= 2; off <<= 1) {
            float b[TOPK], m[TOPK];
            #pragma unroll
            for (int s = 0; s < TOPK; s++)
                b[s] = __shfl_xor_sync(0xffffffffu, t5[r][s], off);
            #pragma unroll
            for (int s = 0; s < TOPK; s++)
                m[s] = fminf(t5[r][s], b[TOPK - 1 - s]);
            CE(m[0], m[1]); CE(m[1], m[2]); CE(m[2], m[3]); CE(m[3], m[4]);
            CE(m[0], m[1]); CE(m[1], m[2]); CE(m[2], m[3]);
            CE(m[0], m[1]); CE(m[1], m[2]);
            CE(m[0], m[1]);
            #pragma unroll
            for (int s = 0; s < TOPK; s++) t5[r][s] = m[s];
        }
    }
    if ((lane & 3) == 0) {
        #pragma unroll
        for (int mf = 0; mf < 4; mf++)
            #pragma unroll
            for (int h = 0; h < 2; h++) {
                int lrow = warpM * 64 + mf * 16 + (lane >> 2) + 8 * h;
                size_t base =
                    ((((size_t)cta * 2 + slot) * 4 + warpN) * 128 + lrow) * TOPK;
                #pragma unroll
                for (int s = 0; s < TOPK; s++)
                    g_cand2[base + s] = t5[mf * 2 + h][s];
            }
    }
}

__global__ __launch_bounds__(256, 1) void mma_main() {
    const int tid   = threadIdx.x;
    const int wid   = tid >> 5;
    const int lane  = tid & 31;
    const int warpM = wid >> 2;      // 0..1 (64 rows each)
    const int warpN = wid & 3;       // 0..3 (64 cols each)
    const int cta   = blockIdx.x;
    const uint32_t sbase = smem_u32(smem);

    const int start = part_start(cta);
    const int end   = part_start(cta + 1);

    const uint32_t rowA_off =
        (uint32_t)(warpM * 64 + ((lane >> 3) & 1) * 8 + (lane & 7)) * ROWB +
        (uint32_t)(lane >> 4) * 16;
    const uint32_t rowB_off =
        (uint32_t)(warpN * 64 + ((lane >> 4) & 1) * 8 + (lane & 7)) * ROWB +
        (uint32_t)((lane >> 3) & 1) * 16;

    const __half2 HINF2 = __half2half2(__ushort_as_half((unsigned short)0x7C00));
    const __half2 NEG2  = __float2half2_rn(-2.0f);

    __half2 sm5[8][8];
    #pragma unroll
    for (int r = 0; r < 8; r++)
        #pragma unroll
        for (int nf = 0; nf < 8; nf++) sm5[r][nf] = HINF2;

    // cached A fragments for k-steps 0..3 (loop-invariant within a segment)
    uint32_t aC[4][4][4];            // [ks][mf][reg]

    // prime B for first item (256 rows = 4096 cp16 chunks)
    {
        const int tb = (start & 63) * NT;
        const char* gB = (const char*)g_tgt_h + (size_t)tb * 256;
        #pragma unroll
        for (int i = 0; i < 16; i++) {
            int cix = tid + i * 256;
            int r = cix >> 4, c = cix & 15;
            cp16(sbase + SB0 + r * ROWB + c * 16, gB + (size_t)r * 256 + c * 16);
        }
        if (tid < 128) cp4(sbase + B2H0 + tid * 4, g_b2h + tb + tid * 2);
        CP_COMMIT();
    }

    int cur_pt = -1, slotidx = -1;

    for (int it = start; it < end; it++) {
        const int pt = it >> 6;
        const int p  = (it - start) & 1;
        const uint32_t sb_cur = sbase + (p ? SB1 : SB0);
        const uint32_t b2_cur = sbase + (p ? B2H1 : B2H0);

        if (pt != cur_pt) {
            if (cur_pt >= 0) {
                flush_sm5(sm5, cta, slotidx, warpM, warpN, lane);
                #pragma unroll
                for (int r = 0; r < 8; r++)
                    #pragma unroll
                    for (int nf = 0; nf < 8; nf++) sm5[r][nf] = HINF2;
            }
            cur_pt = pt;
            slotidx++;
            const char* gA = (const char*)g_pred_h + (size_t)pt * MT * 256;
            #pragma unroll
            for (int i = 0; i < 8; i++) {
                int cix = tid + i * 256;
                int r = cix >> 4, c = cix & 15;
                cp16(sbase + SA + r * ROWB + c * 16, gA + (size_t)r * 256 + c * 16);
            }
            CP_COMMIT();
            CP_WAIT0();
            __syncthreads();
            // load cached A fragments for ks 0..3
            #pragma unroll
            for (int ks = 0; ks < 4; ks++)
                #pragma unroll
                for (int mf = 0; mf < 4; mf++)
                    ldsm4(sbase + SA + rowA_off + mf * (16 * ROWB) + ks * 32,
                          aC[ks][mf][0], aC[ks][mf][1],
                          aC[ks][mf][2], aC[ks][mf][3]);
        }

        // prefetch next B tile
        if (it + 1 < end) {
            const int tbn = ((it + 1) & 63) * NT;
            const uint32_t sb_nxt = sbase + (p ? SB0 : SB1);
            const uint32_t b2_nxt = sbase + (p ? B2H0 : B2H1);
            const char* gB = (const char*)g_tgt_h + (size_t)tbn * 256;
            #pragma unroll
            for (int i = 0; i < 16; i++) {
                int cix = tid + i * 256;
                int r = cix >> 4, c = cix & 15;
                cp16(sb_nxt + r * ROWB + c * 16, gB + (size_t)r * 256 + c * 16);
            }
            if (tid < 128) cp4(b2_nxt + tid * 4, g_b2h + tbn + tid * 2);
            CP_COMMIT();
        }

        // ---- C(64x64, f16 acc) = A_warp(64x128) . B_warp^T ----
        uint32_t acc[4][8][2];
        #pragma unroll
        for (int mf = 0; mf < 4; mf++)
            #pragma unroll
            for (int nf = 0; nf < 8; nf++) {
                acc[mf][nf][0] = 0u;
                acc[mf][nf][1] = 0u;
            }

        // k-steps 0..3: cached A fragments (no A LDSM)
        #pragma unroll
        for (int ks = 0; ks < 4; ks++) {
            #pragma unroll
            for (int j = 0; j < 4; j++) {
                uint32_t b0, b1, b2, b3;
                ldsm4(sb_cur + rowB_off + j * (16 * ROWB) + ks * 32, b0, b1, b2, b3);
                #pragma unroll
                for (int mf = 0; mf < 4; mf++) {
                    mma16816_f16(acc[mf][2 * j + 0][0], acc[mf][2 * j + 0][1],
                                 aC[ks][mf][0], aC[ks][mf][1],
                                 aC[ks][mf][2], aC[ks][mf][3], b0, b1);
                    mma16816_f16(acc[mf][2 * j + 1][0], acc[mf][2 * j + 1][1],
                                 aC[ks][mf][0], aC[ks][mf][1],
                                 aC[ks][mf][2], aC[ks][mf][3], b2, b3);
                }
            }
        }
        // k-steps 4..7: A fragments from smem
        #pragma unroll
        for (int ks = 4; ks < 8; ks++) {
            uint32_t a[4][4];
            #pragma unroll
            for (int mf = 0; mf < 4; mf++)
                ldsm4(sbase + SA + rowA_off + mf * (16 * ROWB) + ks * 32,
                      a[mf][0], a[mf][1], a[mf][2], a[mf][3]);
            #pragma unroll
            for (int j = 0; j < 4; j++) {
                uint32_t b0, b1, b2, b3;
                ldsm4(sb_cur + rowB_off + j * (16 * ROWB) + ks * 32, b0, b1, b2, b3);
                #pragma unroll
                for (int mf = 0; mf < 4; mf++) {
                    mma16816_f16(acc[mf][2 * j + 0][0], acc[mf][2 * j + 0][1],
                                 a[mf][0], a[mf][1], a[mf][2], a[mf][3], b0, b1);
                    mma16816_f16(acc[mf][2 * j + 1][0], acc[mf][2 * j + 1][1],
                                 a[mf][0], a[mf][1], a[mf][2], a[mf][3], b2, b3);
                }
            }
        }

        // ---- epilogue: half2 keys + unconditional stream-min ----
        #pragma unroll
        for (int nf = 0; nf < 8; nf++) {
            uint32_t b2r;
            asm volatile("ld.shared.b32 %0, [%1];" : "=r"(b2r)
                : "r"(b2_cur + (uint32_t)(warpN * 128 + nf * 16 + 4 * (lane & 3))));
            __half2 b2h2 = *reinterpret_cast<__half2*>(&b2r);
            #pragma unroll
            for (int mf = 0; mf < 4; mf++)
                #pragma unroll
                for (int h = 0; h < 2; h++) {
                    __half2 a = *reinterpret_cast<__half2*>(&acc[mf][nf][h]);
                    __half2 key = __hfma2(NEG2, a, b2h2);
                    sm5[mf * 2 + h][nf] = __hmin2(sm5[mf * 2 + h][nf], key);
                }
        }

        CP_WAIT0();
        __syncthreads();
    }

    flush_sm5(sm5, cta, slotidx, warpM, warpN, lane);
}

// ---------------- merge writer-indexed candidates -> final ----------------
__global__ void merge_kernel(float* __restrict__ out) {
    __shared__ float ws[8];
    __shared__ int is_last;
    int r  = blockIdx.x * 256 + threadIdx.x;
    int pt = r >> 7;
    int lr = r & 127;
    int w0 = cta_of(pt << 6);
    int w1 = cta_of((pt << 6) + 63);

    float t5[TOPK];
    #pragma unroll
    for (int s = 0; s < TOPK; s++) t5[s] = FLT_MAX;

    for (int w = w0; w <= w1; w++) {
        int slot = ((part_start(w) >> 6) == pt) ? 0 : 1;
        #pragma unroll
        for (int wn = 0; wn < 4; wn++) {
            size_t base = ((((size_t)w * 2 + slot) * 4 + wn) * 128 + lr) * TOPK;
            #pragma unroll
            for (int s = 0; s < TOPK; s++) {
                float key = g_cand2[base + s];
                INS(t5, key);
            }
        }
    }

    float a2 = g_a2[r];
    float sum = 0.0f;
    #pragma unroll
    for (int s = 0; s < TOPK; s++) {
        float d2 = fmaxf(a2 + t5[s], 0.0f);
        sum += fmaxf(sqrtf(d2) - 1.0f, 0.0f);
    }
    #pragma unroll
    for (int off = 16; off; off >>= 1)
        sum += __shfl_xor_sync(0xffffffffu, sum, off);
    if ((threadIdx.x & 31) == 0) ws[threadIdx.x >> 5] = sum;
    __syncthreads();
    if (threadIdx.x == 0) {
        float t = 0.0f;
        #pragma unroll
        for (int w = 0; w < 8; w++) t += ws[w];
        g_partials[blockIdx.x] = t;
        __threadfence();
        int v = atomicAdd(&g_ticket, 1);
        is_last = (v == 31) ? 1 : 0;
    }
    __syncthreads();
    if (is_last && threadIdx.x == 0) {
        __threadfence();
        float t = 0.0f;
        #pragma unroll
        for (int b = 0; b < 32; b++) t += g_partials[b];   // fixed order
        out[0] = t * (1.0f / ((float)N_PRED * (float)TOPK));
    }
}

extern "C" void kernel_launch(void* const* d_in, const int* in_sizes, int n_in,
                              void* d_out, int out_size) {
    const float* pred = (const float*)d_in[0];
    const float* tgt  = (const float*)d_in[1];

    prep_kernel<<<(N_PRED + M_TGT + 7) / 8, 256>>>(pred, tgt);

    cudaFuncSetAttribute(mma_main, cudaFuncAttributeMaxDynamicSharedMemorySize,
                         SMEM_TOTAL);
    mma_main<<<NCTA, 256, SMEM_TOTAL>>>();

    merge_kernel<<<N_PRED / 256, 256>>>((float*)d_out);
}

// round 14
// speedup vs baseline: 1.0759x; 1.0581x over previous
#include <cuda_runtime.h>
#include <cuda_fp16.h>
#include <math.h>
#include <float.h>
#include <stdint.h>

#define N_PRED 8192
#define M_TGT  16384
#define KD     128
#define MT     128
#define NT     128
#define NITEMS 8192               // 64 pred-tiles * 128 chunks
#define NCTA   296                // 2 per SM
#define TOPK   5
#define ROWB   272                // padded smem row bytes (136 halves)

// ---------------- static device scratch ----------------
__device__ __half g_pred_h[N_PRED * KD];
__device__ __half g_tgt_h[M_TGT * KD];
__device__ float  g_a2[N_PRED];
__device__ __half g_b2h[M_TGT];
// writer-indexed candidates: [cta][ptslot(2)][warpN(2)][128 rows][5]
__device__ float  g_cand2[NCTA * 2 * 2 * 128 * TOPK];
__device__ float  g_partials[32];
__device__ int    g_ticket;

// ---------------- smem layout (bytes), total 104960 ----------------
#define SA    0
#define SB0   34816
#define SB1   69632
#define B2H0  104448
#define B2H1  104704
#define SMEM_TOTAL 104960

__device__ __forceinline__ uint32_t smem_u32(const void* p) {
    uint32_t a;
    asm("{ .reg .u64 t; cvta.to.shared.u64 t, %1; cvt.u32.u64 %0, t; }"
        : "=r"(a) : "l"(p));
    return a;
}
__device__ __forceinline__ void cp16(uint32_t dst, const void* src) {
    asm volatile("cp.async.cg.shared.global [%0], [%1], 16;"
                 :: "r"(dst), "l"(src) : "memory");
}
__device__ __forceinline__ void cp4(uint32_t dst, const void* src) {
    asm volatile("cp.async.ca.shared.global [%0], [%1], 4;"
                 :: "r"(dst), "l"(src) : "memory");
}
#define CP_COMMIT() asm volatile("cp.async.commit_group;" ::: "memory")
#define CP_WAIT0()  asm volatile("cp.async.wait_group 0;" ::: "memory")

__device__ __forceinline__ void ldsm4(uint32_t a, uint32_t& r0, uint32_t& r1,
                                      uint32_t& r2, uint32_t& r3) {
    asm volatile("ldmatrix.sync.aligned.m8n8.x4.shared.b16 {%0,%1,%2,%3}, [%4];"
                 : "=r"(r0), "=r"(r1), "=r"(r2), "=r"(r3) : "r"(a));
}
__device__ __forceinline__ void mma16816_f16(uint32_t& d0, uint32_t& d1,
                                             uint32_t a0, uint32_t a1,
                                             uint32_t a2, uint32_t a3,
                                             uint32_t b0, uint32_t b1) {
    asm volatile("mma.sync.aligned.m16n8k16.row.col.f16.f16.f16.f16 "
                 "{%0,%1}, {%2,%3,%4,%5}, {%6,%7}, {%0,%1};"
                 : "+r"(d0), "+r"(d1)
                 : "r"(a0), "r"(a1), "r"(a2), "r"(a3), "r"(b0), "r"(b1));
}

#define CE(x, y) { float _lo = fminf(x, y); float _hi = fmaxf(x, y); x = _lo; y = _hi; }
#define INS(t, v) \
    if ((v) < (t)[4]) { \
        (t)[4] = (v); \
        CE((t)[3], (t)[4]); CE((t)[2], (t)[3]); \
        CE((t)[1], (t)[2]); CE((t)[0], (t)[1]); \
    }

// closed-form static item partition: start(cta) = cta*27 + min(cta,200)
__host__ __device__ __forceinline__ int part_start(int cta) {
    return cta * 27 + (cta < 200 ? cta : 200);
}
__device__ __forceinline__ int cta_of(int item) {
    return (item < 5600) ? (item / 28) : ((item - 200) / 27);
}

// ---------------- prep: fp32 -> fp16 + norms (4-row batched, MLP=4) ----------------
__global__ void prep_kernel(const float* __restrict__ pred,
                            const float* __restrict__ tgt) {
    if (blockIdx.x == 0 && threadIdx.x == 0) g_ticket = 0;
    const int lane = threadIdx.x & 31;
    const int wid  = threadIdx.x >> 5;
    const int row0 = blockIdx.x * 32 + wid * 4;       // 4 rows per warp
    if (row0 >= N_PRED + M_TGT) return;

    float4 v[4];
    #pragma unroll
    for (int b = 0; b < 4; b++) {
        int r = row0 + b;
        const float* src = (r < M_TGT) ? (tgt + (size_t)r * KD)
                                       : (pred + (size_t)(r - M_TGT) * KD);
        v[b] = ((const float4*)src)[lane];
    }
    #pragma unroll
    for (int b = 0; b < 4; b++) {
        int r = row0 + b;
        float s = v[b].x * v[b].x + v[b].y * v[b].y +
                  v[b].z * v[b].z + v[b].w * v[b].w;
        #pragma unroll
        for (int off = 16; off; off >>= 1)
            s += __shfl_xor_sync(0xffffffffu, s, off);
        __half2 h0 = __floats2half2_rn(v[b].x, v[b].y);
        __half2 h1 = __floats2half2_rn(v[b].z, v[b].w);
        uint2 u;
        u.x = *reinterpret_cast<unsigned*>(&h0);
        u.y = *reinterpret_cast<unsigned*>(&h1);
        __half* dst = (r < M_TGT) ? (g_tgt_h + (size_t)r * KD)
                                  : (g_pred_h + (size_t)(r - M_TGT) * KD);
        *(uint2*)(dst + lane * 4) = u;
        if (lane == 0) {
            if (r < M_TGT) g_b2h[r] = __float2half_rn(s);
            else           g_a2[r - M_TGT] = s;
        }
    }
}

// ---------------- main: balanced HMMA + half2 stream-min top-5 ----------------
extern __shared__ char smem[];

__device__ __forceinline__ void flush_sm5(__half2 (&sm5)[4][8], int cta, int slot,
                                          int warpM, int warpN, int lane) {
    float t5[4][TOPK];
    #pragma unroll
    for (int r = 0; r < 4; r++)
        #pragma unroll
        for (int s = 0; s < TOPK; s++) t5[r][s] = FLT_MAX;
    #pragma unroll
    for (int r = 0; r < 4; r++)
        #pragma unroll
        for (int nf = 0; nf < 8; nf++) {
            float2 f = __half22float2(sm5[r][nf]);
            INS(t5[r], f.x);
            INS(t5[r], f.y);
        }
    // quad merge: lanes 4g..4g+3 share the same rows
    #pragma unroll
    for (int r = 0; r < 4; r++) {
        #pragma unroll
        for (int off = 1; off <= 2; off <<= 1) {
            float b[TOPK], m[TOPK];
            #pragma unroll
            for (int s = 0; s < TOPK; s++)
                b[s] = __shfl_xor_sync(0xffffffffu, t5[r][s], off);
            #pragma unroll
            for (int s = 0; s < TOPK; s++)
                m[s] = fminf(t5[r][s], b[TOPK - 1 - s]);
            CE(m[0], m[1]); CE(m[1], m[2]); CE(m[2], m[3]); CE(m[3], m[4]);
            CE(m[0], m[1]); CE(m[1], m[2]); CE(m[2], m[3]);
            CE(m[0], m[1]); CE(m[1], m[2]);
            CE(m[0], m[1]);
            #pragma unroll
            for (int s = 0; s < TOPK; s++) t5[r][s] = m[s];
        }
    }
    if ((lane & 3) == 0) {
        #pragma unroll
        for (int mf = 0; mf < 2; mf++)
            #pragma unroll
            for (int h = 0; h < 2; h++) {
                int lrow = warpM * 32 + mf * 16 + (lane >> 2) + 8 * h;
                size_t base =
                    ((((size_t)cta * 2 + slot) * 2 + warpN) * 128 + lrow) * TOPK;
                #pragma unroll
                for (int s = 0; s < TOPK; s++)
                    g_cand2[base + s] = t5[mf * 2 + h][s];
            }
    }
}

__global__ __launch_bounds__(256, 2) void mma_main() {
    const int tid   = threadIdx.x;
    const int wid   = tid >> 5;
    const int lane  = tid & 31;
    const int warpM = wid >> 1;
    const int warpN = wid & 1;
    const int cta   = blockIdx.x;
    const uint32_t sbase = smem_u32(smem);

    const int start = part_start(cta);
    const int end   = part_start(cta + 1);

    const uint32_t rowA_off =
        (uint32_t)(warpM * 32 + ((lane >> 3) & 1) * 8 + (lane & 7)) * ROWB +
        (uint32_t)(lane >> 4) * 16;
    const uint32_t rowB_off =
        (uint32_t)(warpN * 64 + ((lane >> 4) & 1) * 8 + (lane & 7)) * ROWB +
        (uint32_t)((lane >> 3) & 1) * 16;

    const __half2 HINF2 = __half2half2(__ushort_as_half((unsigned short)0x7C00));
    const __half2 NEG2  = __float2half2_rn(-2.0f);

    __half2 sm5[4][8];
    #pragma unroll
    for (int r = 0; r < 4; r++)
        #pragma unroll
        for (int nf = 0; nf < 8; nf++) sm5[r][nf] = HINF2;

    // prime B for first item
    {
        const int tb = (start & 127) * NT;
        const char* gB = (const char*)g_tgt_h + (size_t)tb * 256;
        #pragma unroll
        for (int i = 0; i < 8; i++) {
            int cix = tid + i * 256;
            int r = cix >> 4, c = cix & 15;
            cp16(sbase + SB0 + r * ROWB + c * 16, gB + (size_t)r * 256 + c * 16);
        }
        if (tid < 64) cp4(sbase + B2H0 + tid * 4, g_b2h + tb + tid * 2);
        CP_COMMIT();
    }

    int cur_pt = -1, slotidx = -1;

    for (int it = start; it < end; it++) {
        const int pt = it >> 7;
        const int p  = (it - start) & 1;
        const uint32_t sb_cur = sbase + (p ? SB1 : SB0);
        const uint32_t b2_cur = sbase + (p ? B2H1 : B2H0);

        if (pt != cur_pt) {
            if (cur_pt >= 0) {
                flush_sm5(sm5, cta, slotidx, warpM, warpN, lane);
                #pragma unroll
                for (int r = 0; r < 4; r++)
                    #pragma unroll
                    for (int nf = 0; nf < 8; nf++) sm5[r][nf] = HINF2;
            }
            cur_pt = pt;
            slotidx++;
            const char* gA = (const char*)g_pred_h + (size_t)pt * MT * 256;
            #pragma unroll
            for (int i = 0; i < 8; i++) {
                int cix = tid + i * 256;
                int r = cix >> 4, c = cix & 15;
                cp16(sbase + SA + r * ROWB + c * 16, gA + (size_t)r * 256 + c * 16);
            }
            CP_COMMIT();
            CP_WAIT0();
            __syncthreads();
        }

        // prefetch next B tile
        if (it + 1 < end) {
            const int tbn = ((it + 1) & 127) * NT;
            const uint32_t sb_nxt = sbase + (p ? SB0 : SB1);
            const uint32_t b2_nxt = sbase + (p ? B2H0 : B2H1);
            const char* gB = (const char*)g_tgt_h + (size_t)tbn * 256;
            #pragma unroll
            for (int i = 0; i < 8; i++) {
                int cix = tid + i * 256;
                int r = cix >> 4, c = cix & 15;
                cp16(sb_nxt + r * ROWB + c * 16, gB + (size_t)r * 256 + c * 16);
            }
            if (tid < 64) cp4(b2_nxt + tid * 4, g_b2h + tbn + tid * 2);
            CP_COMMIT();
        }

        // ---- C(32x64, f16 acc) = A_warp(32x128) . B_warp^T ----
        uint32_t acc[2][8][2];
        #pragma unroll
        for (int mf = 0; mf < 2; mf++)
            #pragma unroll
            for (int nf = 0; nf < 8; nf++) {
                acc[mf][nf][0] = 0u;
                acc[mf][nf][1] = 0u;
            }

        #pragma unroll
        for (int ks = 0; ks < 8; ks++) {
            // batch ALL fragment loads for this k-step first (6 LDSM),
            // then issue the 16 MMAs — gives the scheduler a full reorder
            // window so LDS latency overlaps MMA issue.
            uint32_t a[2][4], b[4][4];
            #pragma unroll
            for (int mf = 0; mf < 2; mf++)
                ldsm4(sbase + SA + rowA_off + mf * (16 * ROWB) + ks * 32,
                      a[mf][0], a[mf][1], a[mf][2], a[mf][3]);
            #pragma unroll
            for (int j = 0; j < 4; j++)
                ldsm4(sb_cur + rowB_off + j * (16 * ROWB) + ks * 32,
                      b[j][0], b[j][1], b[j][2], b[j][3]);
            #pragma unroll
            for (int j = 0; j < 4; j++)
                #pragma unroll
                for (int mf = 0; mf < 2; mf++) {
                    mma16816_f16(acc[mf][2 * j + 0][0], acc[mf][2 * j + 0][1],
                                 a[mf][0], a[mf][1], a[mf][2], a[mf][3],
                                 b[j][0], b[j][1]);
                    mma16816_f16(acc[mf][2 * j + 1][0], acc[mf][2 * j + 1][1],
                                 a[mf][0], a[mf][1], a[mf][2], a[mf][3],
                                 b[j][2], b[j][3]);
                }
        }

        // ---- epilogue: half2 keys + unconditional stream-min ----
        // process in two halves of 4 nf; batch the 4 b2 loads ahead of use
        #pragma unroll
        for (int half = 0; half < 2; half++) {
            uint32_t b2r[4];
            #pragma unroll
            for (int q = 0; q < 4; q++)
                asm volatile("ld.shared.b32 %0, [%1];" : "=r"(b2r[q])
                    : "r"(b2_cur + (uint32_t)(warpN * 128 + (half * 4 + q) * 16 +
                                              4 * (lane & 3))));
            #pragma unroll
            for (int q = 0; q < 4; q++) {
                const int nf = half * 4 + q;
                __half2 b2h2 = *reinterpret_cast<__half2*>(&b2r[q]);
                #pragma unroll
                for (int mf = 0; mf < 2; mf++)
                    #pragma unroll
                    for (int h = 0; h < 2; h++) {
                        __half2 a2v = *reinterpret_cast<__half2*>(&acc[mf][nf][h]);
                        __half2 key = __hfma2(NEG2, a2v, b2h2);
                        sm5[mf * 2 + h][nf] = __hmin2(sm5[mf * 2 + h][nf], key);
                    }
            }
        }

        CP_WAIT0();
        __syncthreads();
    }

    flush_sm5(sm5, cta, slotidx, warpM, warpN, lane);
}

// ---------------- merge writer-indexed candidates -> final ----------------
__global__ void merge_kernel(float* __restrict__ out) {
    __shared__ float ws[8];
    __shared__ int is_last;
    int r  = blockIdx.x * 256 + threadIdx.x;
    int pt = r >> 7;
    int lr = r & 127;
    int w0 = cta_of(pt << 7);
    int w1 = cta_of((pt << 7) + 127);

    float t5[TOPK];
    #pragma unroll
    for (int s = 0; s < TOPK; s++) t5[s] = FLT_MAX;

    for (int w = w0; w <= w1; w++) {
        int slot = ((part_start(w) >> 7) == pt) ? 0 : 1;
        #pragma unroll
        for (int wn = 0; wn < 2; wn++) {
            size_t base = ((((size_t)w * 2 + slot) * 2 + wn) * 128 + lr) * TOPK;
            #pragma unroll
            for (int s = 0; s < TOPK; s++) {
                float key = g_cand2[base + s];
                INS(t5, key);
            }
        }
    }

    float a2 = g_a2[r];
    float sum = 0.0f;
    #pragma unroll
    for (int s = 0; s < TOPK; s++) {
        float d2 = fmaxf(a2 + t5[s], 0.0f);
        sum += fmaxf(sqrtf(d2) - 1.0f, 0.0f);
    }
    #pragma unroll
    for (int off = 16; off; off >>= 1)
        sum += __shfl_xor_sync(0xffffffffu, sum, off);
    if ((threadIdx.x & 31) == 0) ws[threadIdx.x >> 5] = sum;
    __syncthreads();
    if (threadIdx.x == 0) {
        float t = 0.0f;
        #pragma unroll
        for (int w = 0; w < 8; w++) t += ws[w];
        g_partials[blockIdx.x] = t;
        __threadfence();
        int v = atomicAdd(&g_ticket, 1);
        is_last = (v == 31) ? 1 : 0;
    }
    __syncthreads();
    if (is_last && threadIdx.x == 0) {
        __threadfence();
        float t = 0.0f;
        #pragma unroll
        for (int b = 0; b < 32; b++) t += g_partials[b];   // fixed order
        out[0] = t * (1.0f / ((float)N_PRED * (float)TOPK));
    }
}

extern "C" void kernel_launch(void* const* d_in, const int* in_sizes, int n_in,
                              void* d_out, int out_size) {
    const float* pred = (const float*)d_in[0];
    const float* tgt  = (const float*)d_in[1];

    prep_kernel<<<(N_PRED + M_TGT + 31) / 32, 256>>>(pred, tgt);

    cudaFuncSetAttribute(mma_main, cudaFuncAttributeMaxDynamicSharedMemorySize,
                         SMEM_TOTAL);
    mma_main<<<NCTA, 256, SMEM_TOTAL>>>();

    merge_kernel<<<N_PRED / 256, 256>>>((float*)d_out);
}

// round 15
// speedup vs baseline: 1.1367x; 1.0565x over previous
#include <cuda_runtime.h>
#include <cuda_fp16.h>
#include <math.h>
#include <float.h>
#include <stdint.h>

#define N_PRED 8192
#define M_TGT  16384
#define KD     128
#define MT     128
#define NT     128
#define NITEMS 8192               // 64 pred-tiles * 128 chunks
#define NCTA   296                // 2 per SM
#define TOPK   5
#define ROWB   272                // padded smem row bytes (136 halves)

// ---------------- static device scratch ----------------
__device__ __half g_pred_h[N_PRED * KD];
__device__ __half g_tgt_h[M_TGT * KD];
__device__ float  g_a2[N_PRED];
__device__ __half g_b2h[M_TGT];
// writer-indexed candidates: [cta][ptslot(2)][warpN(2)][128 rows][5]
__device__ float  g_cand2[NCTA * 2 * 2 * 128 * TOPK];
__device__ float  g_partials[32];
__device__ int    g_ticket;

// ---------------- smem layout (bytes), total 104960 ----------------
#define SA    0
#define SB0   34816
#define SB1   69632
#define B2H0  104448
#define B2H1  104704
#define SMEM_TOTAL 104960

__device__ __forceinline__ uint32_t smem_u32(const void* p) {
    uint32_t a;
    asm("{ .reg .u64 t; cvta.to.shared.u64 t, %1; cvt.u32.u64 %0, t; }"
        : "=r"(a) : "l"(p));
    return a;
}
__device__ __forceinline__ void cp16(uint32_t dst, const void* src) {
    asm volatile("cp.async.cg.shared.global [%0], [%1], 16;"
                 :: "r"(dst), "l"(src) : "memory");
}
__device__ __forceinline__ void cp4(uint32_t dst, const void* src) {
    asm volatile("cp.async.ca.shared.global [%0], [%1], 4;"
                 :: "r"(dst), "l"(src) : "memory");
}
#define CP_COMMIT() asm volatile("cp.async.commit_group;" ::: "memory")
#define CP_WAIT0()  asm volatile("cp.async.wait_group 0;" ::: "memory")

__device__ __forceinline__ void ldsm4(uint32_t a, uint32_t& r0, uint32_t& r1,
                                      uint32_t& r2, uint32_t& r3) {
    asm volatile("ldmatrix.sync.aligned.m8n8.x4.shared.b16 {%0,%1,%2,%3}, [%4];"
                 : "=r"(r0), "=r"(r1), "=r"(r2), "=r"(r3) : "r"(a));
}
__device__ __forceinline__ void mma16816_f16(uint32_t& d0, uint32_t& d1,
                                             uint32_t a0, uint32_t a1,
                                             uint32_t a2, uint32_t a3,
                                             uint32_t b0, uint32_t b1) {
    asm volatile("mma.sync.aligned.m16n8k16.row.col.f16.f16.f16.f16 "
                 "{%0,%1}, {%2,%3,%4,%5}, {%6,%7}, {%0,%1};"
                 : "+r"(d0), "+r"(d1)
                 : "r"(a0), "r"(a1), "r"(a2), "r"(a3), "r"(b0), "r"(b1));
}

#define CE(x, y) { float _lo = fminf(x, y); float _hi = fmaxf(x, y); x = _lo; y = _hi; }
#define INS(t, v) \
    if ((v) < (t)[4]) { \
        (t)[4] = (v); \
        CE((t)[3], (t)[4]); CE((t)[2], (t)[3]); \
        CE((t)[1], (t)[2]); CE((t)[0], (t)[1]); \
    }

// closed-form static item partition: start(cta) = cta*27 + min(cta,200)
__host__ __device__ __forceinline__ int part_start(int cta) {
    return cta * 27 + (cta < 200 ? cta : 200);
}
__device__ __forceinline__ int cta_of(int item) {
    return (item < 5600) ? (item / 28) : ((item - 200) / 27);
}

// ---------------- prep: fp32 -> fp16 + norms (4-row batched) ----------------
__global__ void prep_kernel(const float* __restrict__ pred,
                            const float* __restrict__ tgt) {
    if (blockIdx.x == 0 && threadIdx.x == 0) g_ticket = 0;
    const int lane = threadIdx.x & 31;
    const int wid  = threadIdx.x >> 5;
    const int row0 = blockIdx.x * 32 + wid * 4;
    if (row0 >= N_PRED + M_TGT) return;

    float4 v[4];
    #pragma unroll
    for (int b = 0; b < 4; b++) {
        int r = row0 + b;
        const float* src = (r < M_TGT) ? (tgt + (size_t)r * KD)
                                       : (pred + (size_t)(r - M_TGT) * KD);
        v[b] = ((const float4*)src)[lane];
    }
    #pragma unroll
    for (int b = 0; b < 4; b++) {
        int r = row0 + b;
        float s = v[b].x * v[b].x + v[b].y * v[b].y +
                  v[b].z * v[b].z + v[b].w * v[b].w;
        #pragma unroll
        for (int off = 16; off; off >>= 1)
            s += __shfl_xor_sync(0xffffffffu, s, off);
        __half2 h0 = __floats2half2_rn(v[b].x, v[b].y);
        __half2 h1 = __floats2half2_rn(v[b].z, v[b].w);
        uint2 u;
        u.x = *reinterpret_cast<unsigned*>(&h0);
        u.y = *reinterpret_cast<unsigned*>(&h1);
        __half* dst = (r < M_TGT) ? (g_tgt_h + (size_t)r * KD)
                                  : (g_pred_h + (size_t)(r - M_TGT) * KD);
        *(uint2*)(dst + lane * 4) = u;
        if (lane == 0) {
            if (r < M_TGT) g_b2h[r] = __float2half_rn(s);
            else           g_a2[r - M_TGT] = s;
        }
    }
}

// ---------------- main: balanced HMMA + A-frag cache + stream-min ----------------
extern __shared__ char smem[];

__device__ __forceinline__ void flush_sm5(__half2 (&sm5)[4][4], int cta, int slot,
                                          int warpM, int warpN, int lane) {
    float t5[4][TOPK];
    #pragma unroll
    for (int r = 0; r < 4; r++)
        #pragma unroll
        for (int s = 0; s < TOPK; s++) t5[r][s] = FLT_MAX;
    #pragma unroll
    for (int r = 0; r < 4; r++)
        #pragma unroll
        for (int nf = 0; nf < 4; nf++) {
            float2 f = __half22float2(sm5[r][nf]);
            INS(t5[r], f.x);
            INS(t5[r], f.y);
        }
    // quad merge: lanes 4g..4g+3 share the same rows
    #pragma unroll
    for (int r = 0; r < 4; r++) {
        #pragma unroll
        for (int off = 1; off <= 2; off <<= 1) {
            float b[TOPK], m[TOPK];
            #pragma unroll
            for (int s = 0; s < TOPK; s++)
                b[s] = __shfl_xor_sync(0xffffffffu, t5[r][s], off);
            #pragma unroll
            for (int s = 0; s < TOPK; s++)
                m[s] = fminf(t5[r][s], b[TOPK - 1 - s]);
            CE(m[0], m[1]); CE(m[1], m[2]); CE(m[2], m[3]); CE(m[3], m[4]);
            CE(m[0], m[1]); CE(m[1], m[2]); CE(m[2], m[3]);
            CE(m[0], m[1]); CE(m[1], m[2]);
            CE(m[0], m[1]);
            #pragma unroll
            for (int s = 0; s < TOPK; s++) t5[r][s] = m[s];
        }
    }
    if ((lane & 3) == 0) {
        #pragma unroll
        for (int mf = 0; mf < 2; mf++)
            #pragma unroll
            for (int h = 0; h < 2; h++) {
                int lrow = warpM * 32 + mf * 16 + (lane >> 2) + 8 * h;
                size_t base =
                    ((((size_t)cta * 2 + slot) * 2 + warpN) * 128 + lrow) * TOPK;
                #pragma unroll
                for (int s = 0; s < TOPK; s++)
                    g_cand2[base + s] = t5[mf * 2 + h][s];
            }
    }
}

__global__ __launch_bounds__(256, 2) void mma_main() {
    const int tid   = threadIdx.x;
    const int wid   = tid >> 5;
    const int lane  = tid & 31;
    const int warpM = wid >> 1;
    const int warpN = wid & 1;
    const int cta   = blockIdx.x;
    const uint32_t sbase = smem_u32(smem);

    const int start = part_start(cta);
    const int end   = part_start(cta + 1);

    const uint32_t rowA_off =
        (uint32_t)(warpM * 32 + ((lane >> 3) & 1) * 8 + (lane & 7)) * ROWB +
        (uint32_t)(lane >> 4) * 16;
    const uint32_t rowB_off =
        (uint32_t)(warpN * 64 + ((lane >> 4) & 1) * 8 + (lane & 7)) * ROWB +
        (uint32_t)((lane >> 3) & 1) * 16;

    const __half2 HINF2 = __half2half2(__ushort_as_half((unsigned short)0x7C00));
    const __half2 NEG2  = __float2half2_rn(-2.0f);

    __half2 sm5[4][4];               // 16 regs (32 classes per row)
    #pragma unroll
    for (int r = 0; r < 4; r++)
        #pragma unroll
        for (int nf = 0; nf < 4; nf++) sm5[r][nf] = HINF2;

    uint32_t aC[4][2][4];            // cached A frags, k-steps 0..3 (32 regs)

    // prime B for first item
    {
        const int tb = (start & 127) * NT;
        const char* gB = (const char*)g_tgt_h + (size_t)tb * 256;
        #pragma unroll
        for (int i = 0; i < 8; i++) {
            int cix = tid + i * 256;
            int r = cix >> 4, c = cix & 15;
            cp16(sbase + SB0 + r * ROWB + c * 16, gB + (size_t)r * 256 + c * 16);
        }
        if (tid < 64) cp4(sbase + B2H0 + tid * 4, g_b2h + tb + tid * 2);
        CP_COMMIT();
    }

    int cur_pt = -1, slotidx = -1;

    for (int it = start; it < end; it++) {
        const int pt = it >> 7;
        const int p  = (it - start) & 1;
        const uint32_t sb_cur = sbase + (p ? SB1 : SB0);
        const uint32_t b2_cur = sbase + (p ? B2H1 : B2H0);

        if (pt != cur_pt) {
            if (cur_pt >= 0) {
                flush_sm5(sm5, cta, slotidx, warpM, warpN, lane);
                #pragma unroll
                for (int r = 0; r < 4; r++)
                    #pragma unroll
                    for (int nf = 0; nf < 4; nf++) sm5[r][nf] = HINF2;
            }
            cur_pt = pt;
            slotidx++;
            const char* gA = (const char*)g_pred_h + (size_t)pt * MT * 256;
            #pragma unroll
            for (int i = 0; i < 8; i++) {
                int cix = tid + i * 256;
                int r = cix >> 4, c = cix & 15;
                cp16(sbase + SA + r * ROWB + c * 16, gA + (size_t)r * 256 + c * 16);
            }
            CP_COMMIT();
            CP_WAIT0();
            __syncthreads();
            // cache A fragments for k-steps 0..3 (segment-invariant)
            #pragma unroll
            for (int ks = 0; ks < 4; ks++)
                #pragma unroll
                for (int mf = 0; mf < 2; mf++)
                    ldsm4(sbase + SA + rowA_off + mf * (16 * ROWB) + ks * 32,
                          aC[ks][mf][0], aC[ks][mf][1],
                          aC[ks][mf][2], aC[ks][mf][3]);
        }

        // prefetch next B tile
        if (it + 1 < end) {
            const int tbn = ((it + 1) & 127) * NT;
            const uint32_t sb_nxt = sbase + (p ? SB0 : SB1);
            const uint32_t b2_nxt = sbase + (p ? B2H0 : B2H1);
            const char* gB = (const char*)g_tgt_h + (size_t)tbn * 256;
            #pragma unroll
            for (int i = 0; i < 8; i++) {
                int cix = tid + i * 256;
                int r = cix >> 4, c = cix & 15;
                cp16(sb_nxt + r * ROWB + c * 16, gB + (size_t)r * 256 + c * 16);
            }
            if (tid < 64) cp4(b2_nxt + tid * 4, g_b2h + tbn + tid * 2);
            CP_COMMIT();
        }

        // ---- C(32x64, f16 acc) = A_warp(32x128) . B_warp^T ----
        uint32_t acc[2][8][2];
        #pragma unroll
        for (int mf = 0; mf < 2; mf++)
            #pragma unroll
            for (int nf = 0; nf < 8; nf++) {
                acc[mf][nf][0] = 0u;
                acc[mf][nf][1] = 0u;
            }

        // k-steps 0..3: cached A (no A LDSM), interleaved B-LDSM + MMA
        #pragma unroll
        for (int ks = 0; ks < 4; ks++) {
            #pragma unroll
            for (int j = 0; j < 4; j++) {
                uint32_t b0, b1, b2, b3;
                ldsm4(sb_cur + rowB_off + j * (16 * ROWB) + ks * 32, b0, b1, b2, b3);
                #pragma unroll
                for (int mf = 0; mf < 2; mf++) {
                    mma16816_f16(acc[mf][2 * j + 0][0], acc[mf][2 * j + 0][1],
                                 aC[ks][mf][0], aC[ks][mf][1],
                                 aC[ks][mf][2], aC[ks][mf][3], b0, b1);
                    mma16816_f16(acc[mf][2 * j + 1][0], acc[mf][2 * j + 1][1],
                                 aC[ks][mf][0], aC[ks][mf][1],
                                 aC[ks][mf][2], aC[ks][mf][3], b2, b3);
                }
            }
        }
        // k-steps 4..7: A from smem (R11 interleave)
        #pragma unroll
        for (int ks = 4; ks < 8; ks++) {
            uint32_t a[2][4];
            #pragma unroll
            for (int mf = 0; mf < 2; mf++)
                ldsm4(sbase + SA + rowA_off + mf * (16 * ROWB) + ks * 32,
                      a[mf][0], a[mf][1], a[mf][2], a[mf][3]);
            #pragma unroll
            for (int j = 0; j < 4; j++) {
                uint32_t b0, b1, b2, b3;
                ldsm4(sb_cur + rowB_off + j * (16 * ROWB) + ks * 32, b0, b1, b2, b3);
                #pragma unroll
                for (int mf = 0; mf < 2; mf++) {
                    mma16816_f16(acc[mf][2 * j + 0][0], acc[mf][2 * j + 0][1],
                                 a[mf][0], a[mf][1], a[mf][2], a[mf][3], b0, b1);
                    mma16816_f16(acc[mf][2 * j + 1][0], acc[mf][2 * j + 1][1],
                                 a[mf][0], a[mf][1], a[mf][2], a[mf][3], b2, b3);
                }
            }
        }

        // ---- epilogue: half2 keys + stream-min into folded classes ----
        #pragma unroll
        for (int nf = 0; nf < 8; nf++) {
            uint32_t b2r;
            asm volatile("ld.shared.b32 %0, [%1];" : "=r"(b2r)
                : "r"(b2_cur + (uint32_t)(warpN * 128 + nf * 16 + 4 * (lane & 3))));
            __half2 b2h2 = *reinterpret_cast<__half2*>(&b2r);
            #pragma unroll
            for (int mf = 0; mf < 2; mf++)
                #pragma unroll
                for (int h = 0; h < 2; h++) {
                    __half2 a2v = *reinterpret_cast<__half2*>(&acc[mf][nf][h]);
                    __half2 key = __hfma2(NEG2, a2v, b2h2);
                    sm5[mf * 2 + h][nf & 3] = __hmin2(sm5[mf * 2 + h][nf & 3], key);
                }
        }

        CP_WAIT0();
        __syncthreads();
    }

    flush_sm5(sm5, cta, slotidx, warpM, warpN, lane);
}

// ---------------- merge writer-indexed candidates -> final ----------------
__global__ void merge_kernel(float* __restrict__ out) {
    __shared__ float ws[8];
    __shared__ int is_last;
    int r  = blockIdx.x * 256 + threadIdx.x;
    int pt = r >> 7;
    int lr = r & 127;
    int w0 = cta_of(pt << 7);
    int w1 = cta_of((pt << 7) + 127);

    float t5[TOPK];
    #pragma unroll
    for (int s = 0; s < TOPK; s++) t5[s] = FLT_MAX;

    for (int w = w0; w <= w1; w++) {
        int slot = ((part_start(w) >> 7) == pt) ? 0 : 1;
        #pragma unroll
        for (int wn = 0; wn < 2; wn++) {
            size_t base = ((((size_t)w * 2 + slot) * 2 + wn) * 128 + lr) * TOPK;
            #pragma unroll
            for (int s = 0; s < TOPK; s++) {
                float key = g_cand2[base + s];
                INS(t5, key);
            }
        }
    }

    float a2 = g_a2[r];
    float sum = 0.0f;
    #pragma unroll
    for (int s = 0; s < TOPK; s++) {
        float d2 = fmaxf(a2 + t5[s], 0.0f);
        sum += fmaxf(sqrtf(d2) - 1.0f, 0.0f);
    }
    #pragma unroll
    for (int off = 16; off; off >>= 1)
        sum += __shfl_xor_sync(0xffffffffu, sum, off);
    if ((threadIdx.x & 31) == 0) ws[threadIdx.x >> 5] = sum;
    __syncthreads();
    if (threadIdx.x == 0) {
        float t = 0.0f;
        #pragma unroll
        for (int w = 0; w < 8; w++) t += ws[w];
        g_partials[blockIdx.x] = t;
        __threadfence();
        int v = atomicAdd(&g_ticket, 1);
        is_last = (v == 31) ? 1 : 0;
    }
    __syncthreads();
    if (is_last && threadIdx.x == 0) {
        __threadfence();
        float t = 0.0f;
        #pragma unroll
        for (int b = 0; b < 32; b++) t += g_partials[b];   // fixed order
        out[0] = t * (1.0f / ((float)N_PRED * (float)TOPK));
    }
}

extern "C" void kernel_launch(void* const* d_in, const int* in_sizes, int n_in,
                              void* d_out, int out_size) {
    const float* pred = (const float*)d_in[0];
    const float* tgt  = (const float*)d_in[1];

    prep_kernel<<<(N_PRED + M_TGT + 31) / 32, 256>>>(pred, tgt);

    cudaFuncSetAttribute(mma_main, cudaFuncAttributeMaxDynamicSharedMemorySize,
                         SMEM_TOTAL);
    mma_main<<<NCTA, 256, SMEM_TOTAL>>>();

    merge_kernel<<<N_PRED / 256, 256>>>((float*)d_out);
}